// round 11
// baseline (speedup 1.0000x reference)
#include <cuda_runtime.h>
#include <cuda_fp16.h>
#include <math.h>
#include <stdint.h>

// Problem dims (fixed by the dataset)
#define B_   256
#define T_   256
#define D_   128
#define H_   512
#define G3H  1536
#define BT   (B_ * T_)

// ---------------------------------------------------------------------------
// Scratch (static device allocations; harness forbids cudaMalloc)
// ---------------------------------------------------------------------------
__device__ float g_xg[(size_t)BT * G3H];   // xg0 (layer-0 input projections)
__device__ float g_hT[B_ * H_];            // final hidden of layer 1
// h fragments, A-layout, fp16 hi/lo, double buffered
__device__ uint4 g_h0frag[2][2][16 * 32 * 32];
__device__ uint4 g_h1frag[2][2][16 * 32 * 32];

// Slot barrier: each block owns one 128B line; monotonic gens, snapshot at
// kernel start -> replay-safe.
__device__ volatile unsigned g_slot[4][32][32];

__device__ __forceinline__ void slot_barrier(int grp, int blk, unsigned gen) {
    __syncthreads();
    if (threadIdx.x == 0) {
        __threadfence();                    // release own writes
        g_slot[grp][blk][0] = gen;
    }
    if (threadIdx.x < 32) {
        while ((int)(g_slot[grp][threadIdx.x][0] - gen) < 0) { }
        __threadfence();                    // acquire
    }
    __syncthreads();
}

// ---------------------------------------------------------------------------
// math helpers
// ---------------------------------------------------------------------------
__device__ __forceinline__ uint32_t f2tf(float f) {
    uint32_t u;
    asm("cvt.rna.tf32.f32 %0, %1;" : "=r"(u) : "f"(f));
    return u;
}

__device__ __forceinline__ void mma_tf32(float* c, const uint32_t* a, const uint32_t* b) {
    asm volatile(
        "mma.sync.aligned.m16n8k8.row.col.f32.tf32.tf32.f32 "
        "{%0,%1,%2,%3}, {%4,%5,%6,%7}, {%8,%9}, {%0,%1,%2,%3};\n"
        : "+f"(c[0]), "+f"(c[1]), "+f"(c[2]), "+f"(c[3])
        : "r"(a[0]), "r"(a[1]), "r"(a[2]), "r"(a[3]), "r"(b[0]), "r"(b[1]));
}

// fp16 mma m16n8k16, fp32 accum
__device__ __forceinline__ void mma_f16(float* c, const uint4& a, uint32_t b0, uint32_t b1) {
    asm volatile(
        "mma.sync.aligned.m16n8k16.row.col.f32.f16.f16.f32 "
        "{%0,%1,%2,%3}, {%4,%5,%6,%7}, {%8,%9}, {%0,%1,%2,%3};\n"
        : "+f"(c[0]), "+f"(c[1]), "+f"(c[2]), "+f"(c[3])
        : "r"(a.x), "r"(a.y), "r"(a.z), "r"(a.w), "r"(b0), "r"(b1));
}

__device__ __forceinline__ uint32_t pack2_f16(float e0, float e1) {
    __half2 t = __floats2half2_rn(e0, e1);  // .x = low half
    return *(uint32_t*)&t;
}

__device__ __forceinline__ float sigf(float x) {
    return 1.0f / (1.0f + __expf(-x));
}

// Build fp16 B-fragments for a 48-col x 512-k weight tile.
// Column order: n = tile*8 + q, tile = gate*2 + jhalf -> weight row
// gate*H + j0 + jhalf*8 + q. Each C-fragment thread then owns all 3 gates of
// its 4 j-columns (gate math in registers) AND a full A-fragment on store.
__device__ __forceinline__ void build_wfrag_f16(
    uint32_t* Wu, const float* __restrict__ Wsrc, int j0, int tid, int slot_off)
{
    for (int idx = tid; idx < 48 * 256; idx += 512) {
        int n  = idx >> 8;
        int k  = (idx & 255) << 1;
        int tile = n >> 3, q = n & 7;
        int gate = tile >> 1, jh = tile & 1;
        const float* wrow = Wsrc + ((size_t)(gate * H_ + j0 + jh * 8 + q)) * H_;
        uint32_t v = pack2_f16(wrow[k], wrow[k + 1]);
        int ks = k >> 4, kr = k & 15;
        int rr = (kr >= 8) ? 1 : 0;
        int lw = q * 4 + ((kr >> 1) & 3);
        Wu[((((slot_off + tile) * 32 + ks) * 32 + lw) << 1) + rr] = v;
    }
}

// Per-warp 16x48 GEMM over NKS k-slices: fp16 weights (smem), fp16 hi/lo A
// (global frags), ks-parity-split accumulators, 2-pair-deep A prefetch.
template<int NKS>
__device__ __forceinline__ void gemm6_f16(
    float Ca[3][2][4], float Cb[3][2][4],
    const uint2* __restrict__ Ws, int wbase, int koff,
    const uint4* __restrict__ Ahi, const uint4* __restrict__ Alo,
    size_t fb0, int lane)
{
    uint4 bh[2][2], bl[2][2];
#pragma unroll
    for (int p = 0; p < 2; p++) {
        bh[p][0] = Ahi[fb0 + (2 * p) * 32];     bl[p][0] = Alo[fb0 + (2 * p) * 32];
        bh[p][1] = Ahi[fb0 + (2 * p + 1) * 32]; bl[p][1] = Alo[fb0 + (2 * p + 1) * 32];
    }
    const int npairs = NKS >> 1;
#pragma unroll 4
    for (int kp = 0; kp < npairs; kp++) {
        const int pb = kp & 1;
        uint4 a0h = bh[pb][0], a0l = bl[pb][0];
        uint4 a1h = bh[pb][1], a1l = bl[pb][1];
        if (kp + 2 < npairs) {
            bh[pb][0] = Ahi[fb0 + (2 * kp + 4) * 32]; bl[pb][0] = Alo[fb0 + (2 * kp + 4) * 32];
            bh[pb][1] = Ahi[fb0 + (2 * kp + 5) * 32]; bl[pb][1] = Alo[fb0 + (2 * kp + 5) * 32];
        }
#pragma unroll
        for (int tl = 0; tl < 6; tl++) {
            const int gt = tl >> 1, jh = tl & 1;
            uint2 w0 = Ws[((wbase + tl) * 32 + koff + 2 * kp) * 32 + lane];
            mma_f16(Ca[gt][jh], a0h, w0.x, w0.y);
            mma_f16(Ca[gt][jh], a0l, w0.x, w0.y);
            uint2 w1 = Ws[((wbase + tl) * 32 + koff + 2 * kp + 1) * 32 + lane];
            mma_f16(Cb[gt][jh], a1h, w1.x, w1.y);
            mma_f16(Cb[gt][jh], a1l, w1.x, w1.y);
        }
    }
}

// ---------------------------------------------------------------------------
// tf32 tensor-core GEMM (phase 1): xg0 = x @ Wih0^T + bih0   (unchanged)
// ---------------------------------------------------------------------------
__global__ void __launch_bounds__(256) gemm_tf32_kernel(
    const float* __restrict__ A, const float* __restrict__ W,
    const float* __restrict__ bias, int K, float* __restrict__ C)
{
    __shared__ uint32_t As[128][36];
    __shared__ uint32_t Bs[128][36];

    const int tid  = threadIdx.x;
    const int m0   = blockIdx.y * 128;
    const int n0   = blockIdx.x * 128;
    const int warp = tid >> 5, lane = tid & 31;
    const int wm = warp >> 2, wn = warp & 3;
    const int g  = lane >> 2, tg = lane & 3;

    float acc[4][4][4] = {};

    for (int k0 = 0; k0 < K; k0 += 32) {
#pragma unroll
        for (int r = 0; r < 4; r++) {
            int f   = tid + (r << 8);
            int row = f >> 3;
            int c4  = (f & 7) << 2;
            float4 va = *(const float4*)(A + (size_t)(m0 + row) * K + k0 + c4);
            As[row][c4 + 0] = f2tf(va.x);
            As[row][c4 + 1] = f2tf(va.y);
            As[row][c4 + 2] = f2tf(va.z);
            As[row][c4 + 3] = f2tf(va.w);
            float4 vb = *(const float4*)(W + (size_t)(n0 + row) * K + k0 + c4);
            Bs[row][c4 + 0] = f2tf(vb.x);
            Bs[row][c4 + 1] = f2tf(vb.y);
            Bs[row][c4 + 2] = f2tf(vb.z);
            Bs[row][c4 + 3] = f2tf(vb.w);
        }
        __syncthreads();

#pragma unroll
        for (int s = 0; s < 4; s++) {
            const int kb = s << 3;
            uint32_t a[4][4], b[4][2];
#pragma unroll
            for (int i = 0; i < 4; i++) {
                int r0 = wm * 64 + i * 16 + g;
                a[i][0] = As[r0][kb + tg];
                a[i][1] = As[r0 + 8][kb + tg];
                a[i][2] = As[r0][kb + tg + 4];
                a[i][3] = As[r0 + 8][kb + tg + 4];
            }
#pragma unroll
            for (int jx = 0; jx < 4; jx++) {
                int c = wn * 32 + jx * 8 + g;
                b[jx][0] = Bs[c][kb + tg];
                b[jx][1] = Bs[c][kb + tg + 4];
            }
#pragma unroll
            for (int i = 0; i < 4; i++)
#pragma unroll
                for (int jx = 0; jx < 4; jx++)
                    mma_tf32(acc[i][jx], a[i], b[jx]);
        }
        __syncthreads();
    }

#pragma unroll
    for (int i = 0; i < 4; i++) {
        int r0 = m0 + wm * 64 + i * 16 + g;
#pragma unroll
        for (int jx = 0; jx < 4; jx++) {
            int col = n0 + wn * 32 + jx * 8 + tg * 2;
            float2 bv = *(const float2*)(bias + col);
            float2 o0 = make_float2(acc[i][jx][0] + bv.x, acc[i][jx][1] + bv.y);
            float2 o1 = make_float2(acc[i][jx][2] + bv.x, acc[i][jx][3] + bv.y);
            *(float2*)(C + (size_t)r0 * G3H + col)       = o0;
            *(float2*)(C + (size_t)(r0 + 8) * G3H + col) = o1;
        }
    }
}

// ---------------------------------------------------------------------------
// MERGED two-layer GRU, fp16 weights all in smem, dedup'd A reads.
// Window t:
//   task0 (warps 0-7):  h0(t) = GRU0(h0(t-1), xg0[t]); wn splits K-halves
//   task1 (warps 8-15): h1(t-1) = GRU1(h1(t-2), h0(t-1)); wn0 = ih-side GEMM
//                       (A0 @ Wih1), wn1 = hh-side GEMM (A1 @ Whh1)
// Partials recombine via a conflict-free smem exchange + ONE __syncthreads.
// Gate math + h-frag stores fully register-resident in the wn0 threads.
// ---------------------------------------------------------------------------
#define XS 25

__global__ void __launch_bounds__(512, 1) gru_merged_kernel(
    const float* __restrict__ Whh0, const float* __restrict__ bhh0,
    const float* __restrict__ Whh1, const float* __restrict__ bhh1,
    const float* __restrict__ Wih1, const float* __restrict__ bih1)
{
    extern __shared__ char smraw[];
    uint2* Ws  = (uint2*)smraw;                         // 18 slots x 32ks x 32 lanes = 144KB
    float* Xsm = (float*)(smraw + 18 * 32 * 32 * 8);    // [2][128][XS] = 25.6KB

    const int tid = threadIdx.x;
    const int bid = blockIdx.x;
    const int jt = bid & 31, mt = bid >> 5;
    const int m0 = mt * 64, j0 = jt * 16;
    const int w = tid >> 5, lane = tid & 31;
    const int task = w >> 3, wsub = w & 7;
    const int wm = wsub >> 1, wn = wsub & 1;
    const int g = lane >> 2, tg = lane & 3;
    const int m16 = mt * 4 + wm;

    unsigned bgen = 0;
    if (tid < 32) bgen = g_slot[mt][jt][0];
    unsigned genc = 0;

    build_wfrag_f16((uint32_t*)Ws, Whh0, j0, tid, 0);
    build_wfrag_f16((uint32_t*)Ws, Whh1, j0, tid, 6);
    build_wfrag_f16((uint32_t*)Ws, Wih1, j0, tid, 12);

    // Zero h0frag buf0 (h0(-1)) and h1frag buf1 (h1(-1)), group-local slices
    {
        int idx = (bid & 31) * 512 + tid;      // 0..16383
        size_t base = (size_t)mt * 4096;
        uint4 z = make_uint4(0, 0, 0, 0);
        if      (idx < 4096)  g_h0frag[0][0][base + idx] = z;
        else if (idx < 8192)  g_h0frag[0][1][base + idx - 4096] = z;
        else if (idx < 12288) g_h1frag[1][0][base + idx - 8192] = z;
        else                  g_h1frag[1][1][base + idx - 12288] = z;
    }

    const int mrow0 = m0 + wm * 16 + g;
    const int mrow1 = mrow0 + 8;
    const int jcb   = j0 + 2 * tg;            // column base; +jh*8 per half

    // biases (wn0 threads only use these)
    float2 br0[2], bz0[2], bn0[2];             // task 0
    float2 Br1[2], Bz1[2], bxn1[2], bhn1[2];   // task 1
    if (wn == 0) {
#pragma unroll
        for (int jh = 0; jh < 2; jh++) {
            int c = jcb + jh * 8;
            if (task == 0) {
                br0[jh] = *(const float2*)&bhh0[c];
                bz0[jh] = *(const float2*)&bhh0[H_ + c];
                bn0[jh] = *(const float2*)&bhh0[2 * H_ + c];
            } else {
                float2 a1 = *(const float2*)&bih1[c];
                float2 a2 = *(const float2*)&bhh1[c];
                Br1[jh] = make_float2(a1.x + a2.x, a1.y + a2.y);
                a1 = *(const float2*)&bih1[H_ + c];
                a2 = *(const float2*)&bhh1[H_ + c];
                Bz1[jh] = make_float2(a1.x + a2.x, a1.y + a2.y);
                bxn1[jh] = *(const float2*)&bih1[2 * H_ + c];
                bhn1[jh] = *(const float2*)&bhh1[2 * H_ + c];
            }
        }
    }

    float hreg[2][4] = {};
    float2 xr[2][2], xz[2][2], xn[2][2];   // [row][jh]

    auto prefetch_xg = [&](int tt) {
#pragma unroll
        for (int r2 = 0; r2 < 2; r2++) {
            size_t mb = ((size_t)(r2 ? mrow1 : mrow0) * T_ + tt) * G3H;
#pragma unroll
            for (int jh = 0; jh < 2; jh++) {
                int c = jcb + jh * 8;
                xr[r2][jh] = *(const float2*)&g_xg[mb + c];
                xz[r2][jh] = *(const float2*)&g_xg[mb + H_ + c];
                xn[r2][jh] = *(const float2*)&g_xg[mb + 2 * H_ + c];
            }
        }
    };
    if (task == 0 && wn == 0) prefetch_xg(0);

    slot_barrier(mt, jt, bgen + (++genc));

    const size_t fb_base = (size_t)(m16 * 32) * 32 + lane;
    const size_t sb      = ((size_t)(m16 * 32) + jt) * 32 + lane;

    for (int t = 0; t <= T_; t++) {
        float Ca[3][2][4] = {}, Cb[3][2][4] = {};
        bool did_mma = false;

        if (task == 0) {
            if (t < T_) {
                gemm6_f16<16>(Ca, Cb, Ws, 0, wn * 16,
                              g_h0frag[t & 1][0], g_h0frag[t & 1][1],
                              fb_base + (size_t)(wn * 16) * 32, lane);
                did_mma = true;
            }
        } else if (t >= 1) {
            if (wn == 0)
                gemm6_f16<32>(Ca, Cb, Ws, 12, 0,
                              g_h0frag[t & 1][0], g_h0frag[t & 1][1], fb_base, lane);
            else
                gemm6_f16<32>(Ca, Cb, Ws, 6, 0,
                              g_h1frag[t & 1][0], g_h1frag[t & 1][1], fb_base, lane);
            did_mma = true;
        }

        // wn1 publishes partials
        if (did_mma && wn == 1) {
            float* X = Xsm + (size_t)(task * 128 + wm * 32 + lane) * XS;
#pragma unroll
            for (int gt = 0; gt < 3; gt++)
#pragma unroll
                for (int jh = 0; jh < 2; jh++)
#pragma unroll
                    for (int ci = 0; ci < 4; ci++)
                        X[gt * 8 + jh * 4 + ci] = Ca[gt][jh][ci] + Cb[gt][jh][ci];
        }
        __syncthreads();

        // wn0 combines + gate math + stores
        if (did_mma && wn == 0) {
            const float* X = Xsm + (size_t)(task * 128 + wm * 32 + lane) * XS;
            float hv[2][4];
#pragma unroll
            for (int jh = 0; jh < 2; jh++) {
#pragma unroll
                for (int ci = 0; ci < 4; ci++) {
                    int rw = ci >> 1, p = ci & 1;
                    float cr = Ca[0][jh][ci] + Cb[0][jh][ci] + X[jh * 4 + ci];
                    float cz = Ca[1][jh][ci] + Cb[1][jh][ci] + X[8 + jh * 4 + ci];
                    float cn = Ca[2][jh][ci] + Cb[2][jh][ci] + X[16 + jh * 4 + ci];
                    float r, z, nv;
                    if (task == 0) {
                        float xrv = p ? xr[rw][jh].y : xr[rw][jh].x;
                        float xzv = p ? xz[rw][jh].y : xz[rw][jh].x;
                        float xnv = p ? xn[rw][jh].y : xn[rw][jh].x;
                        r  = sigf(xrv + cr + (p ? br0[jh].y : br0[jh].x));
                        z  = sigf(xzv + cz + (p ? bz0[jh].y : bz0[jh].x));
                        nv = tanhf(xnv + r * (cn + (p ? bn0[jh].y : bn0[jh].x)));
                    } else {
                        // cr/cz/cn = ih parts; X = hh parts (already added for r,z)
                        r  = sigf(cr + (p ? Br1[jh].y : Br1[jh].x));
                        z  = sigf(cz + (p ? Bz1[jh].y : Bz1[jh].x));
                        float cni = Ca[2][jh][ci] + Cb[2][jh][ci];
                        float cnh = X[16 + jh * 4 + ci];
                        nv = tanhf(cni + (p ? bxn1[jh].y : bxn1[jh].x)
                                   + r * (cnh + (p ? bhn1[jh].y : bhn1[jh].x)));
                    }
                    float h = (1.0f - z) * nv + z * hreg[jh][ci];
                    hreg[jh][ci] = h;
                    hv[jh][ci] = h;
                }
            }

            if (task == 1 && t == T_) {
#pragma unroll
                for (int jh = 0; jh < 2; jh++) {
                    int c = jcb + jh * 8;
                    *(float2*)(g_hT + (size_t)mrow0 * H_ + c) = make_float2(hv[jh][0], hv[jh][1]);
                    *(float2*)(g_hT + (size_t)mrow1 * H_ + c) = make_float2(hv[jh][2], hv[jh][3]);
                }
            } else {
                float fl[2][4];
#pragma unroll
                for (int jh = 0; jh < 2; jh++)
#pragma unroll
                    for (int ci = 0; ci < 4; ci++)
                        fl[jh][ci] = hv[jh][ci]
                            - __half2float(__float2half_rn(hv[jh][ci]));
                uint4 hi, lo;
                hi.x = pack2_f16(hv[0][0], hv[0][1]); hi.y = pack2_f16(hv[0][2], hv[0][3]);
                hi.z = pack2_f16(hv[1][0], hv[1][1]); hi.w = pack2_f16(hv[1][2], hv[1][3]);
                lo.x = pack2_f16(fl[0][0], fl[0][1]); lo.y = pack2_f16(fl[0][2], fl[0][3]);
                lo.z = pack2_f16(fl[1][0], fl[1][1]); lo.w = pack2_f16(fl[1][2], fl[1][3]);
                const int nb = (t + 1) & 1;
                if (task == 0) {
                    g_h0frag[nb][0][sb] = hi;
                    g_h0frag[nb][1][sb] = lo;
                    if (t < T_ - 1) prefetch_xg(t + 1);
                } else {
                    g_h1frag[nb][0][sb] = hi;
                    g_h1frag[nb][1][sb] = lo;
                }
            }
        }

        slot_barrier(mt, jt, bgen + (++genc));
    }
}

// ---------------------------------------------------------------------------
// Head: out = relu(relu(hT) @ fc1^T + b1) @ fc2^T + b2
// ---------------------------------------------------------------------------
__global__ void __launch_bounds__(512) head_kernel(
    const float* __restrict__ w1, const float* __restrict__ b1,
    const float* __restrict__ w2, const float* __restrict__ b2,
    float* __restrict__ out)
{
    __shared__ float sh[H_];
    __shared__ float s1[128];
    const int b = blockIdx.x;
    const int tid = threadIdx.x;
    const int w = tid >> 5, lane = tid & 31;

    sh[tid] = fmaxf(g_hT[(size_t)b * H_ + tid], 0.0f);
    __syncthreads();

#pragma unroll
    for (int oo = 0; oo < 8; oo++) {
        int o = w * 8 + oo;
        const float* wr = w1 + (size_t)o * H_;
        float acc = 0.f;
#pragma unroll
        for (int c = 0; c < 4; c++) {
            int k = c * 128 + lane * 4;
            float4 wv = *(const float4*)(wr + k);
            float4 hv = *(const float4*)(&sh[k]);
            acc += wv.x * hv.x + wv.y * hv.y + wv.z * hv.z + wv.w * hv.w;
        }
#pragma unroll
        for (int off = 16; off; off >>= 1)
            acc += __shfl_down_sync(0xFFFFFFFFu, acc, off);
        if (lane == 0) s1[o] = fmaxf(acc + b1[o], 0.0f);
    }
    __syncthreads();

    if (w < 10) {
        const float* wr = w2 + (size_t)w * 128;
        float acc = 0.f;
#pragma unroll
        for (int c = 0; c < 4; c++) {
            int k = lane + c * 32;
            acc += s1[k] * wr[k];
        }
#pragma unroll
        for (int off = 16; off; off >>= 1)
            acc += __shfl_down_sync(0xFFFFFFFFu, acc, off);
        if (lane == 0) out[(size_t)b * 10 + w] = acc + b2[w];
    }
}

// ---------------------------------------------------------------------------
// Launch
// ---------------------------------------------------------------------------
extern "C" void kernel_launch(void* const* d_in, const int* in_sizes, int n_in,
                              void* d_out, int out_size)
{
    const float* x    = (const float*)d_in[0];
    const float* Wih0 = (const float*)d_in[1];
    const float* Whh0 = (const float*)d_in[2];
    const float* bih0 = (const float*)d_in[3];
    const float* bhh0 = (const float*)d_in[4];
    const float* Wih1 = (const float*)d_in[5];
    const float* Whh1 = (const float*)d_in[6];
    const float* bih1 = (const float*)d_in[7];
    const float* bhh1 = (const float*)d_in[8];
    const float* fc1w = (const float*)d_in[9];
    const float* fc1b = (const float*)d_in[10];
    const float* fc2w = (const float*)d_in[11];
    const float* fc2b = (const float*)d_in[12];
    float* out = (float*)d_out;

    float* xg_ptr = nullptr;
    cudaGetSymbolAddress((void**)&xg_ptr, g_xg);

    const int merged_smem = 18 * 32 * 32 * 8 + 2 * 128 * XS * 4;  // 144KB + 25.6KB
    cudaFuncSetAttribute((const void*)gru_merged_kernel,
                         cudaFuncAttributeMaxDynamicSharedMemorySize, merged_smem);

    dim3 gemm_grid(G3H / 128, BT / 128);  // (12, 512)

    // Phase 1: xg0 = x @ W_ih0^T + b_ih0   (K = 128)
    gemm_tf32_kernel<<<gemm_grid, 256>>>(x, Wih0, bih0, D_, xg_ptr);

    // Phase 2: merged two-layer GRU (257 barrier windows)
    gru_merged_kernel<<<128, 512, merged_smem>>>(Whh0, bhh0, Whh1, bhh1, Wih1, bih1);

    // Phase 3: MLP head
    head_kernel<<<B_, 512>>>(fc1w, fc1b, fc2w, fc2b, out);
}

// round 12
// speedup vs baseline: 1.2223x; 1.2223x over previous
#include <cuda_runtime.h>
#include <cuda_fp16.h>
#include <math.h>
#include <stdint.h>

// Problem dims (fixed by the dataset)
#define B_   256
#define T_   256
#define D_   128
#define H_   512
#define G3H  1536
#define BT   (B_ * T_)

// ---------------------------------------------------------------------------
// Scratch (static device allocations; harness forbids cudaMalloc)
// ---------------------------------------------------------------------------
__device__ float g_xg[(size_t)BT * G3H];   // xg0 (layer-0 input projections)
__device__ float g_hT[B_ * H_];            // final hidden of layer 1
__device__ uint2 g_wfrag1[32 * 6144];      // Wih1 fp16 fragments per jt (1.5MB, L2)
// h fragments, A-layout, fp16 hi/lo, double buffered
__device__ uint4 g_h0frag[2][2][16 * 32 * 32];
__device__ uint4 g_h1frag[2][2][16 * 32 * 32];

// Slot barrier: each block owns one 128B line; monotonic gens, snapshot at
// kernel start (only the owner writes its slot; all blocks of a group store
// the same number of gens per kernel) -> replay-safe.
__device__ volatile unsigned g_slot[4][32][32];

__device__ __forceinline__ void slot_barrier(int grp, int blk, unsigned gen) {
    __syncthreads();
    if (threadIdx.x == 0) {
        __threadfence();                    // release own writes
        g_slot[grp][blk][0] = gen;
    }
    if (threadIdx.x < 32) {
        while ((int)(g_slot[grp][threadIdx.x][0] - gen) < 0) { }
        __threadfence();                    // acquire
    }
    __syncthreads();
}

// ---------------------------------------------------------------------------
// math helpers
// ---------------------------------------------------------------------------
__device__ __forceinline__ uint32_t f2tf(float f) {
    uint32_t u;
    asm("cvt.rna.tf32.f32 %0, %1;" : "=r"(u) : "f"(f));
    return u;
}

__device__ __forceinline__ void mma_tf32(float* c, const uint32_t* a, const uint32_t* b) {
    asm volatile(
        "mma.sync.aligned.m16n8k8.row.col.f32.tf32.tf32.f32 "
        "{%0,%1,%2,%3}, {%4,%5,%6,%7}, {%8,%9}, {%0,%1,%2,%3};\n"
        : "+f"(c[0]), "+f"(c[1]), "+f"(c[2]), "+f"(c[3])
        : "r"(a[0]), "r"(a[1]), "r"(a[2]), "r"(a[3]), "r"(b[0]), "r"(b[1]));
}

// fp16 mma m16n8k16, fp32 accum
__device__ __forceinline__ void mma_f16(float* c, const uint4& a, uint32_t b0, uint32_t b1) {
    asm volatile(
        "mma.sync.aligned.m16n8k16.row.col.f32.f16.f16.f32 "
        "{%0,%1,%2,%3}, {%4,%5,%6,%7}, {%8,%9}, {%0,%1,%2,%3};\n"
        : "+f"(c[0]), "+f"(c[1]), "+f"(c[2]), "+f"(c[3])
        : "r"(a.x), "r"(a.y), "r"(a.z), "r"(a.w), "r"(b0), "r"(b1));
}

__device__ __forceinline__ uint32_t pack2_f16(float e0, float e1) {
    __half2 t = __floats2half2_rn(e0, e1);  // .x = low half
    return *(uint32_t*)&t;
}

__device__ __forceinline__ float sigf(float x) {
    return 1.0f / (1.0f + __expf(-x));
}

// Build fp16 B-fragments for a 48-col x 512-k weight tile with the GATE-LOCAL
// column order (n = wn*24 + gate*8 + jl -> row gate*H + j0 + wn*8 + jl).
// All 3 gates of a hidden unit land in the SAME C-fragment thread.
__device__ __forceinline__ void build_wfrag_f16(
    uint32_t* Wu, const float* __restrict__ Wsrc, int j0, int tid, int slot_off, int nthreads)
{
    for (int idx = tid; idx < 48 * 256; idx += nthreads) {
        int n  = idx >> 8;
        int k  = (idx & 255) << 1;
        int wn_t = n / 24;
        int rem  = n - wn_t * 24;
        int gate = rem >> 3, jl = rem & 7;
        const float* wrow = Wsrc + ((size_t)(gate * H_ + j0 + wn_t * 8 + jl)) * H_;
        uint32_t v = pack2_f16(wrow[k], wrow[k + 1]);
        int nt = (n >> 3) + slot_off;
        int ks = k >> 4, kr = k & 15;
        int rr = (kr >= 8) ? 1 : 0;
        int lw = (n & 7) * 4 + ((kr >> 1) & 3);
        Wu[(((nt * 32 + ks) * 32 + lw) << 1) + rr] = v;
    }
}

// Setup: Wih1 fp16 fragments to an L2-resident global table (slots 0..5 per jt)
__global__ void __launch_bounds__(512) build_wih1_kernel(const float* __restrict__ Wih1) {
    int jt = blockIdx.x;
    build_wfrag_f16((uint32_t*)(g_wfrag1 + (size_t)jt * 6144), Wih1, jt * 16, threadIdx.x, 0, 512);
}

// 16x48 (per warp) GEMM over npairs*2 k-slices: fp16 weights (2 MMAs per site),
// ks-parity-split accumulators, register double-buffered A-frags.
__device__ __forceinline__ void gemm48_f16(
    float C[3][4], const uint2* __restrict__ Wf, int slot, int koff,
    const uint4* __restrict__ Ahi, const uint4* __restrict__ Alo,
    size_t fb0, int lane, int npairs)
{
    float Ca[3][4] = {}, Cb[3][4] = {};
    uint4 ah0 = Ahi[fb0],      al0 = Alo[fb0];
    uint4 ah1 = Ahi[fb0 + 32], al1 = Alo[fb0 + 32];
#pragma unroll 4
    for (int kp = 0; kp < npairs; kp++) {
        uint4 nh0, nl0, nh1, nl1;
        if (kp < npairs - 1) {
            nh0 = Ahi[fb0 + (2 * kp + 2) * 32]; nl0 = Alo[fb0 + (2 * kp + 2) * 32];
            nh1 = Ahi[fb0 + (2 * kp + 3) * 32]; nl1 = Alo[fb0 + (2 * kp + 3) * 32];
        }
#pragma unroll
        for (int nt = 0; nt < 3; nt++) {
            uint2 w0 = Wf[((slot + nt) * 32 + koff + 2 * kp) * 32 + lane];
            mma_f16(Ca[nt], ah0, w0.x, w0.y);
            mma_f16(Ca[nt], al0, w0.x, w0.y);
            uint2 w1 = Wf[((slot + nt) * 32 + koff + 2 * kp + 1) * 32 + lane];
            mma_f16(Cb[nt], ah1, w1.x, w1.y);
            mma_f16(Cb[nt], al1, w1.x, w1.y);
        }
        ah0 = nh0; al0 = nl0; ah1 = nh1; al1 = nl1;
    }
#pragma unroll
    for (int nt = 0; nt < 3; nt++)
#pragma unroll
        for (int i = 0; i < 4; i++)
            C[nt][i] = Ca[nt][i] + Cb[nt][i];
}

// ---------------------------------------------------------------------------
// tf32 tensor-core GEMM (phase 1): xg0 = x @ Wih0^T + bih0
// ---------------------------------------------------------------------------
__global__ void __launch_bounds__(256) gemm_tf32_kernel(
    const float* __restrict__ A, const float* __restrict__ W,
    const float* __restrict__ bias, int K, float* __restrict__ C)
{
    __shared__ uint32_t As[128][36];
    __shared__ uint32_t Bs[128][36];

    const int tid  = threadIdx.x;
    const int m0   = blockIdx.y * 128;
    const int n0   = blockIdx.x * 128;
    const int warp = tid >> 5, lane = tid & 31;
    const int wm = warp >> 2, wn = warp & 3;
    const int g  = lane >> 2, tg = lane & 3;

    float acc[4][4][4] = {};

    for (int k0 = 0; k0 < K; k0 += 32) {
#pragma unroll
        for (int r = 0; r < 4; r++) {
            int f   = tid + (r << 8);
            int row = f >> 3;
            int c4  = (f & 7) << 2;
            float4 va = *(const float4*)(A + (size_t)(m0 + row) * K + k0 + c4);
            As[row][c4 + 0] = f2tf(va.x);
            As[row][c4 + 1] = f2tf(va.y);
            As[row][c4 + 2] = f2tf(va.z);
            As[row][c4 + 3] = f2tf(va.w);
            float4 vb = *(const float4*)(W + (size_t)(n0 + row) * K + k0 + c4);
            Bs[row][c4 + 0] = f2tf(vb.x);
            Bs[row][c4 + 1] = f2tf(vb.y);
            Bs[row][c4 + 2] = f2tf(vb.z);
            Bs[row][c4 + 3] = f2tf(vb.w);
        }
        __syncthreads();

#pragma unroll
        for (int s = 0; s < 4; s++) {
            const int kb = s << 3;
            uint32_t a[4][4], b[4][2];
#pragma unroll
            for (int i = 0; i < 4; i++) {
                int r0 = wm * 64 + i * 16 + g;
                a[i][0] = As[r0][kb + tg];
                a[i][1] = As[r0 + 8][kb + tg];
                a[i][2] = As[r0][kb + tg + 4];
                a[i][3] = As[r0 + 8][kb + tg + 4];
            }
#pragma unroll
            for (int jx = 0; jx < 4; jx++) {
                int c = wn * 32 + jx * 8 + g;
                b[jx][0] = Bs[c][kb + tg];
                b[jx][1] = Bs[c][kb + tg + 4];
            }
#pragma unroll
            for (int i = 0; i < 4; i++)
#pragma unroll
                for (int jx = 0; jx < 4; jx++)
                    mma_tf32(acc[i][jx], a[i], b[jx]);
        }
        __syncthreads();
    }

#pragma unroll
    for (int i = 0; i < 4; i++) {
        int r0 = m0 + wm * 64 + i * 16 + g;
#pragma unroll
        for (int jx = 0; jx < 4; jx++) {
            int col = n0 + wn * 32 + jx * 8 + tg * 2;
            float2 bv = *(const float2*)(bias + col);
            float2 o0 = make_float2(acc[i][jx][0] + bv.x, acc[i][jx][1] + bv.y);
            float2 o1 = make_float2(acc[i][jx][2] + bv.x, acc[i][jx][3] + bv.y);
            *(float2*)(C + (size_t)r0 * G3H + col)       = o0;
            *(float2*)(C + (size_t)(r0 + 8) * G3H + col) = o1;
        }
    }
}

// ---------------------------------------------------------------------------
// MERGED two-layer GRU (round-10 topology, fp16 weights). 257 windows.
//   warps 0-7  (task 0): h0(t)   = GRU0(h0(t-1), xg0[t])          [t < 256]
//   warps 8-15 (task 1): h1(t-1) = GRU1(h1(t-2), y0(t-1)=h0(t-1)) [t >= 1]
// Whh0+Whh1 fp16 frags in smem (96KB); Wih1 fp16 frags from L2 table with
// 1-ahead register prefetch. All gate math register-resident; no intra-window
// __syncthreads.
// ---------------------------------------------------------------------------
__global__ void __launch_bounds__(512, 1) gru_merged_kernel(
    const float* __restrict__ Whh0, const float* __restrict__ bhh0,
    const float* __restrict__ Whh1, const float* __restrict__ bhh1,
    const float* __restrict__ bih1)
{
    extern __shared__ char smraw[];
    uint2* Wf = (uint2*)smraw;   // slots 0-5: Whh0, slots 6-11: Whh1 (96KB)

    const int tid = threadIdx.x;
    const int bid = blockIdx.x;
    const int jt = bid & 31, mt = bid >> 5;
    const int m0 = mt * 64, j0 = jt * 16;
    const int w = tid >> 5, lane = tid & 31;
    const int task = w >> 3, wsub = w & 7;
    const int wm = wsub >> 1, wn = wsub & 1;
    const int g = lane >> 2, tg = lane & 3;
    const int m16 = mt * 4 + wm;

    unsigned bgen = 0;
    if (tid < 32) bgen = g_slot[mt][jt][0];
    unsigned genc = 0;

    build_wfrag_f16((uint32_t*)Wf, Whh0, j0, tid, 0, 512);
    build_wfrag_f16((uint32_t*)Wf, Whh1, j0, tid, 6, 512);

    // Zero h0frag buf0 (h0(-1)) and h1frag buf1 (h1(-1)), group-local slices
    {
        int idx = (bid & 31) * 512 + tid;      // 0..16383
        size_t base = (size_t)mt * 4096;
        uint4 z = make_uint4(0, 0, 0, 0);
        if      (idx < 4096)  g_h0frag[0][0][base + idx] = z;
        else if (idx < 8192)  g_h0frag[0][1][base + idx - 4096] = z;
        else if (idx < 12288) g_h1frag[1][0][base + idx - 8192] = z;
        else                  g_h1frag[1][1][base + idx - 12288] = z;
    }

    const int jc    = j0 + wn * 8 + 2 * tg;   // this thread's first j column
    const int mrow0 = m0 + wm * 16 + g;       // this thread's rows
    const int mrow1 = mrow0 + 8;

    // biases
    float br0[2], bz0[2], bn0[2];             // task 0
    float Br1[2], Bz1[2], bxn1[2], bhn1[2];   // task 1
    if (task == 0) {
        br0[0] = bhh0[jc];          br0[1] = bhh0[jc + 1];
        bz0[0] = bhh0[H_ + jc];     bz0[1] = bhh0[H_ + jc + 1];
        bn0[0] = bhh0[2 * H_ + jc]; bn0[1] = bhh0[2 * H_ + jc + 1];
    } else {
#pragma unroll
        for (int c = 0; c < 2; c++) {
            Br1[c]  = bih1[jc + c] + bhh1[jc + c];
            Bz1[c]  = bih1[H_ + jc + c] + bhh1[H_ + jc + c];
            bxn1[c] = bih1[2 * H_ + jc + c];
            bhn1[c] = bhh1[2 * H_ + jc + c];
        }
    }

    float hreg[4] = {0.f, 0.f, 0.f, 0.f};
    float xr[4], xz[4], xn[4];

    auto prefetch_xg = [&](int tt) {
        size_t b0 = ((size_t)mrow0 * T_ + tt) * G3H + jc;
        size_t b1 = ((size_t)mrow1 * T_ + tt) * G3H + jc;
        float2 v;
        v = *(const float2*)(g_xg + b0);           xr[0] = v.x; xr[1] = v.y;
        v = *(const float2*)(g_xg + b0 + H_);      xz[0] = v.x; xz[1] = v.y;
        v = *(const float2*)(g_xg + b0 + 2 * H_);  xn[0] = v.x; xn[1] = v.y;
        v = *(const float2*)(g_xg + b1);           xr[2] = v.x; xr[3] = v.y;
        v = *(const float2*)(g_xg + b1 + H_);      xz[2] = v.x; xz[3] = v.y;
        v = *(const float2*)(g_xg + b1 + 2 * H_);  xn[2] = v.x; xn[3] = v.y;
    };
    if (task == 0) prefetch_xg(0);

    slot_barrier(mt, jt, bgen + (++genc));

    const size_t fb0 = (size_t)(m16 * 32) * 32 + lane;
    const size_t sb  = ((size_t)(m16 * 32) + jt) * 32 + lane;
    const uint2* __restrict__ Wg = g_wfrag1 + (size_t)jt * 6144;  // Wih1 table

    for (int t = 0; t <= T_; t++) {
        if (task == 0) {
            if (t < T_) {
                const uint4* __restrict__ Ahi = g_h0frag[t & 1][0];
                const uint4* __restrict__ Alo = g_h0frag[t & 1][1];
                float C[3][4];
                gemm48_f16(C, Wf, wn * 3, 0, Ahi, Alo, fb0, lane, 16);

                float hv[4];
#pragma unroll
                for (int i = 0; i < 4; i++) {
                    float r  = sigf(xr[i] + C[0][i] + br0[i & 1]);
                    float z  = sigf(xz[i] + C[1][i] + bz0[i & 1]);
                    float nv = tanhf(xn[i] + r * (C[2][i] + bn0[i & 1]));
                    float h  = (1.0f - z) * nv + z * hreg[i];
                    hreg[i] = h; hv[i] = h;
                }
                float fl[4];
#pragma unroll
                for (int q = 0; q < 4; q++)
                    fl[q] = hv[q] - __half2float(__float2half_rn(hv[q]));
                uint2 hiu = make_uint2(pack2_f16(hv[0], hv[1]), pack2_f16(hv[2], hv[3]));
                uint2 lou = make_uint2(pack2_f16(fl[0], fl[1]), pack2_f16(fl[2], fl[3]));
                const int nb = (t + 1) & 1;
                ((uint2*)&g_h0frag[nb][0][sb])[wn] = hiu;
                ((uint2*)&g_h0frag[nb][1][sb])[wn] = lou;

                if (t < T_ - 1) prefetch_xg(t + 1);
            }
        } else if (t >= 1) {
            const uint4* __restrict__ A0h = g_h0frag[t & 1][0];
            const uint4* __restrict__ A0l = g_h0frag[t & 1][1];
            const uint4* __restrict__ A1h = g_h1frag[t & 1][0];
            const uint4* __restrict__ A1l = g_h1frag[t & 1][1];

            // 6 independent accumulator chains: {r,z,n} x {ih, hh}
            float Cri[4] = {}, Crh[4] = {}, Czi[4] = {}, Czh[4] = {};
            float Cni[4] = {}, Cnh[4] = {};

            uint4 a0h = A0h[fb0], a0l = A0l[fb0];
            uint4 a1h = A1h[fb0], a1l = A1l[fb0];
            uint2 wi0 = Wg[((wn * 3 + 0) * 32) * 32 + lane];
            uint2 wi1 = Wg[((wn * 3 + 1) * 32) * 32 + lane];
            uint2 wi2 = Wg[((wn * 3 + 2) * 32) * 32 + lane];

#pragma unroll 4
            for (int ks = 0; ks < 32; ks++) {
                uint4 n0h, n0l, n1h, n1l;
                uint2 nw0, nw1, nw2;
                if (ks < 31) {
                    size_t nf = fb0 + (ks + 1) * 32;
                    n0h = A0h[nf]; n0l = A0l[nf];
                    n1h = A1h[nf]; n1l = A1l[nf];
                    nw0 = Wg[((wn * 3 + 0) * 32 + ks + 1) * 32 + lane];
                    nw1 = Wg[((wn * 3 + 1) * 32 + ks + 1) * 32 + lane];
                    nw2 = Wg[((wn * 3 + 2) * 32 + ks + 1) * 32 + lane];
                }
                // hh-side (Whh1, smem slots 6..11) against h1(t-2)
                uint2 wh0 = Wf[((6 + wn * 3 + 0) * 32 + ks) * 32 + lane];
                mma_f16(Crh, a1h, wh0.x, wh0.y);
                mma_f16(Crh, a1l, wh0.x, wh0.y);
                uint2 wh1 = Wf[((6 + wn * 3 + 1) * 32 + ks) * 32 + lane];
                mma_f16(Czh, a1h, wh1.x, wh1.y);
                mma_f16(Czh, a1l, wh1.x, wh1.y);
                uint2 wh2 = Wf[((6 + wn * 3 + 2) * 32 + ks) * 32 + lane];
                mma_f16(Cnh, a1h, wh2.x, wh2.y);
                mma_f16(Cnh, a1l, wh2.x, wh2.y);
                // ih-side (Wih1, global table) against h0(t-1)
                mma_f16(Cri, a0h, wi0.x, wi0.y);
                mma_f16(Cri, a0l, wi0.x, wi0.y);
                mma_f16(Czi, a0h, wi1.x, wi1.y);
                mma_f16(Czi, a0l, wi1.x, wi1.y);
                mma_f16(Cni, a0h, wi2.x, wi2.y);
                mma_f16(Cni, a0l, wi2.x, wi2.y);

                a0h = n0h; a0l = n0l; a1h = n1h; a1l = n1l;
                wi0 = nw0; wi1 = nw1; wi2 = nw2;
            }

            float hv[4];
#pragma unroll
            for (int i = 0; i < 4; i++) {
                float r  = sigf(Cri[i] + Crh[i] + Br1[i & 1]);
                float z  = sigf(Czi[i] + Czh[i] + Bz1[i & 1]);
                float nv = tanhf(Cni[i] + bxn1[i & 1] + r * (Cnh[i] + bhn1[i & 1]));
                float h  = (1.0f - z) * nv + z * hreg[i];
                hreg[i] = h; hv[i] = h;
            }
            if (t == T_) {
                *(float2*)(g_hT + (size_t)mrow0 * H_ + jc) = make_float2(hv[0], hv[1]);
                *(float2*)(g_hT + (size_t)mrow1 * H_ + jc) = make_float2(hv[2], hv[3]);
            } else {
                float fl[4];
#pragma unroll
                for (int q = 0; q < 4; q++)
                    fl[q] = hv[q] - __half2float(__float2half_rn(hv[q]));
                uint2 hiu = make_uint2(pack2_f16(hv[0], hv[1]), pack2_f16(hv[2], hv[3]));
                uint2 lou = make_uint2(pack2_f16(fl[0], fl[1]), pack2_f16(fl[2], fl[3]));
                const int nb = (t + 1) & 1;
                ((uint2*)&g_h1frag[nb][0][sb])[wn] = hiu;
                ((uint2*)&g_h1frag[nb][1][sb])[wn] = lou;
            }
        }

        slot_barrier(mt, jt, bgen + (++genc));
    }
}

// ---------------------------------------------------------------------------
// Head: out = relu(relu(hT) @ fc1^T + b1) @ fc2^T + b2
// ---------------------------------------------------------------------------
__global__ void __launch_bounds__(512) head_kernel(
    const float* __restrict__ w1, const float* __restrict__ b1,
    const float* __restrict__ w2, const float* __restrict__ b2,
    float* __restrict__ out)
{
    __shared__ float sh[H_];
    __shared__ float s1[128];
    const int b = blockIdx.x;
    const int tid = threadIdx.x;
    const int w = tid >> 5, lane = tid & 31;

    sh[tid] = fmaxf(g_hT[(size_t)b * H_ + tid], 0.0f);
    __syncthreads();

#pragma unroll
    for (int oo = 0; oo < 8; oo++) {
        int o = w * 8 + oo;
        const float* wr = w1 + (size_t)o * H_;
        float acc = 0.f;
#pragma unroll
        for (int c = 0; c < 4; c++) {
            int k = c * 128 + lane * 4;
            float4 wv = *(const float4*)(wr + k);
            float4 hv = *(const float4*)(&sh[k]);
            acc += wv.x * hv.x + wv.y * hv.y + wv.z * hv.z + wv.w * hv.w;
        }
#pragma unroll
        for (int off = 16; off; off >>= 1)
            acc += __shfl_down_sync(0xFFFFFFFFu, acc, off);
        if (lane == 0) s1[o] = fmaxf(acc + b1[o], 0.0f);
    }
    __syncthreads();

    if (w < 10) {
        const float* wr = w2 + (size_t)w * 128;
        float acc = 0.f;
#pragma unroll
        for (int c = 0; c < 4; c++) {
            int k = lane + c * 32;
            acc += s1[k] * wr[k];
        }
#pragma unroll
        for (int off = 16; off; off >>= 1)
            acc += __shfl_down_sync(0xFFFFFFFFu, acc, off);
        if (lane == 0) out[(size_t)b * 10 + w] = acc + b2[w];
    }
}

// ---------------------------------------------------------------------------
// Launch
// ---------------------------------------------------------------------------
extern "C" void kernel_launch(void* const* d_in, const int* in_sizes, int n_in,
                              void* d_out, int out_size)
{
    const float* x    = (const float*)d_in[0];
    const float* Wih0 = (const float*)d_in[1];
    const float* Whh0 = (const float*)d_in[2];
    const float* bih0 = (const float*)d_in[3];
    const float* bhh0 = (const float*)d_in[4];
    const float* Wih1 = (const float*)d_in[5];
    const float* Whh1 = (const float*)d_in[6];
    const float* bih1 = (const float*)d_in[7];
    const float* bhh1 = (const float*)d_in[8];
    const float* fc1w = (const float*)d_in[9];
    const float* fc1b = (const float*)d_in[10];
    const float* fc2w = (const float*)d_in[11];
    const float* fc2b = (const float*)d_in[12];
    float* out = (float*)d_out;

    float* xg_ptr = nullptr;
    cudaGetSymbolAddress((void**)&xg_ptr, g_xg);

    const int merged_smem = 12 * 32 * 32 * 8;   // 96KB
    cudaFuncSetAttribute((const void*)gru_merged_kernel,
                         cudaFuncAttributeMaxDynamicSharedMemorySize, merged_smem);

    dim3 gemm_grid(G3H / 128, BT / 128);  // (12, 512)

    // Phase 0: Wih1 fp16 fragment table (1.5MB, L2-resident)
    build_wih1_kernel<<<32, 512>>>(Wih1);

    // Phase 1: xg0 = x @ W_ih0^T + b_ih0   (K = 128)
    gemm_tf32_kernel<<<gemm_grid, 256>>>(x, Wih0, bih0, D_, xg_ptr);

    // Phase 2: merged two-layer GRU (257 barrier windows)
    gru_merged_kernel<<<128, 512, merged_smem>>>(Whh0, bhh0, Whh1, bhh1, bih1);

    // Phase 3: MLP head
    head_kernel<<<B_, 512>>>(fc1w, fc1b, fc2w, fc2b, out);
}

// round 13
// speedup vs baseline: 1.6596x; 1.3578x over previous
#include <cuda_runtime.h>
#include <cuda_fp16.h>
#include <math.h>
#include <stdint.h>

// Problem dims (fixed by the dataset)
#define B_   256
#define T_   256
#define D_   128
#define H_   512
#define G3H  1536
#define BT   (B_ * T_)

// ---------------------------------------------------------------------------
// Scratch (static device allocations; harness forbids cudaMalloc)
// ---------------------------------------------------------------------------
__device__ float g_xg[(size_t)BT * G3H];   // xg0 (layer-0 input projections)
__device__ float g_hT[B_ * H_];            // final hidden of layer 1
__device__ uint2 g_wfrag1[32 * 6144];      // Wih1 fp16 fragments per jt (1.5MB, L2)
// h fragments, A-layout, fp16 SINGLE (state itself stays fp32 in registers),
// double buffered
__device__ uint4 g_h0frag[2][16 * 32 * 32];
__device__ uint4 g_h1frag[2][16 * 32 * 32];

// Slot barrier: each block owns one 128B line; monotonic gens, snapshot at
// kernel start (only the owner writes its slot; all blocks of a group store
// the same number of gens per kernel) -> replay-safe.
__device__ volatile unsigned g_slot[4][32][32];

__device__ __forceinline__ void slot_barrier(int grp, int blk, unsigned gen) {
    __syncthreads();
    if (threadIdx.x == 0) {
        __threadfence();                    // release own writes
        g_slot[grp][blk][0] = gen;
    }
    if (threadIdx.x < 32) {
        while ((int)(g_slot[grp][threadIdx.x][0] - gen) < 0) { }
        __threadfence();                    // acquire
    }
    __syncthreads();
}

// ---------------------------------------------------------------------------
// math helpers
// ---------------------------------------------------------------------------
__device__ __forceinline__ uint32_t f2tf(float f) {
    uint32_t u;
    asm("cvt.rna.tf32.f32 %0, %1;" : "=r"(u) : "f"(f));
    return u;
}

__device__ __forceinline__ void mma_tf32(float* c, const uint32_t* a, const uint32_t* b) {
    asm volatile(
        "mma.sync.aligned.m16n8k8.row.col.f32.tf32.tf32.f32 "
        "{%0,%1,%2,%3}, {%4,%5,%6,%7}, {%8,%9}, {%0,%1,%2,%3};\n"
        : "+f"(c[0]), "+f"(c[1]), "+f"(c[2]), "+f"(c[3])
        : "r"(a[0]), "r"(a[1]), "r"(a[2]), "r"(a[3]), "r"(b[0]), "r"(b[1]));
}

// fp16 mma m16n8k16, fp32 accum
__device__ __forceinline__ void mma_f16(float* c, const uint4& a, uint32_t b0, uint32_t b1) {
    asm volatile(
        "mma.sync.aligned.m16n8k16.row.col.f32.f16.f16.f32 "
        "{%0,%1,%2,%3}, {%4,%5,%6,%7}, {%8,%9}, {%0,%1,%2,%3};\n"
        : "+f"(c[0]), "+f"(c[1]), "+f"(c[2]), "+f"(c[3])
        : "r"(a.x), "r"(a.y), "r"(a.z), "r"(a.w), "r"(b0), "r"(b1));
}

__device__ __forceinline__ uint32_t pack2_f16(float e0, float e1) {
    __half2 t = __floats2half2_rn(e0, e1);  // .x = low half
    return *(uint32_t*)&t;
}

__device__ __forceinline__ float sigf(float x) {
    return 1.0f / (1.0f + __expf(-x));
}

// Build fp16 B-fragments for a 48-col x 512-k weight tile with the GATE-LOCAL
// column order (n = wn*24 + gate*8 + jl -> row gate*H + j0 + wn*8 + jl).
// All 3 gates of a hidden unit land in the SAME C-fragment thread.
__device__ __forceinline__ void build_wfrag_f16(
    uint32_t* Wu, const float* __restrict__ Wsrc, int j0, int tid, int slot_off, int nthreads)
{
    for (int idx = tid; idx < 48 * 256; idx += nthreads) {
        int n  = idx >> 8;
        int k  = (idx & 255) << 1;
        int wn_t = n / 24;
        int rem  = n - wn_t * 24;
        int gate = rem >> 3, jl = rem & 7;
        const float* wrow = Wsrc + ((size_t)(gate * H_ + j0 + wn_t * 8 + jl)) * H_;
        uint32_t v = pack2_f16(wrow[k], wrow[k + 1]);
        int nt = (n >> 3) + slot_off;
        int ks = k >> 4, kr = k & 15;
        int rr = (kr >= 8) ? 1 : 0;
        int lw = (n & 7) * 4 + ((kr >> 1) & 3);
        Wu[(((nt * 32 + ks) * 32 + lw) << 1) + rr] = v;
    }
}

// Setup: Wih1 fp16 fragments to an L2-resident global table (slots 0..5 per jt)
__global__ void __launch_bounds__(512) build_wih1_kernel(const float* __restrict__ Wih1) {
    int jt = blockIdx.x;
    build_wfrag_f16((uint32_t*)(g_wfrag1 + (size_t)jt * 6144), Wih1, jt * 16, threadIdx.x, 0, 512);
}

// 16x48 (per warp) GEMM over 32 k-slices: fp16 weights (smem), fp16 single-A,
// ks-parity-split accumulators, 4-ks-deep A ring prefetch.
__device__ __forceinline__ void gemm48_h(
    float C[3][4], const uint2* __restrict__ Wf, int slot,
    const uint4* __restrict__ A, size_t fb0, int lane)
{
    float Ca[3][4] = {}, Cb[3][4] = {};
    uint4 buf[2][2];
    buf[0][0] = A[fb0];      buf[0][1] = A[fb0 + 32];
    buf[1][0] = A[fb0 + 64]; buf[1][1] = A[fb0 + 96];
#pragma unroll 4
    for (int kp = 0; kp < 16; kp++) {
        const int pb = kp & 1;
        uint4 a0 = buf[pb][0], a1 = buf[pb][1];
        if (kp + 2 < 16) {
            buf[pb][0] = A[fb0 + (2 * kp + 4) * 32];
            buf[pb][1] = A[fb0 + (2 * kp + 5) * 32];
        }
#pragma unroll
        for (int nt = 0; nt < 3; nt++) {
            uint2 w0 = Wf[((slot + nt) * 32 + 2 * kp) * 32 + lane];
            mma_f16(Ca[nt], a0, w0.x, w0.y);
            uint2 w1 = Wf[((slot + nt) * 32 + 2 * kp + 1) * 32 + lane];
            mma_f16(Cb[nt], a1, w1.x, w1.y);
        }
    }
#pragma unroll
    for (int nt = 0; nt < 3; nt++)
#pragma unroll
        for (int i = 0; i < 4; i++)
            C[nt][i] = Ca[nt][i] + Cb[nt][i];
}

// ---------------------------------------------------------------------------
// tf32 tensor-core GEMM (phase 1): xg0 = x @ Wih0^T + bih0
// ---------------------------------------------------------------------------
__global__ void __launch_bounds__(256) gemm_tf32_kernel(
    const float* __restrict__ A, const float* __restrict__ W,
    const float* __restrict__ bias, int K, float* __restrict__ C)
{
    __shared__ uint32_t As[128][36];
    __shared__ uint32_t Bs[128][36];

    const int tid  = threadIdx.x;
    const int m0   = blockIdx.y * 128;
    const int n0   = blockIdx.x * 128;
    const int warp = tid >> 5, lane = tid & 31;
    const int wm = warp >> 2, wn = warp & 3;
    const int g  = lane >> 2, tg = lane & 3;

    float acc[4][4][4] = {};

    for (int k0 = 0; k0 < K; k0 += 32) {
#pragma unroll
        for (int r = 0; r < 4; r++) {
            int f   = tid + (r << 8);
            int row = f >> 3;
            int c4  = (f & 7) << 2;
            float4 va = *(const float4*)(A + (size_t)(m0 + row) * K + k0 + c4);
            As[row][c4 + 0] = f2tf(va.x);
            As[row][c4 + 1] = f2tf(va.y);
            As[row][c4 + 2] = f2tf(va.z);
            As[row][c4 + 3] = f2tf(va.w);
            float4 vb = *(const float4*)(W + (size_t)(n0 + row) * K + k0 + c4);
            Bs[row][c4 + 0] = f2tf(vb.x);
            Bs[row][c4 + 1] = f2tf(vb.y);
            Bs[row][c4 + 2] = f2tf(vb.z);
            Bs[row][c4 + 3] = f2tf(vb.w);
        }
        __syncthreads();

#pragma unroll
        for (int s = 0; s < 4; s++) {
            const int kb = s << 3;
            uint32_t a[4][4], b[4][2];
#pragma unroll
            for (int i = 0; i < 4; i++) {
                int r0 = wm * 64 + i * 16 + g;
                a[i][0] = As[r0][kb + tg];
                a[i][1] = As[r0 + 8][kb + tg];
                a[i][2] = As[r0][kb + tg + 4];
                a[i][3] = As[r0 + 8][kb + tg + 4];
            }
#pragma unroll
            for (int jx = 0; jx < 4; jx++) {
                int c = wn * 32 + jx * 8 + g;
                b[jx][0] = Bs[c][kb + tg];
                b[jx][1] = Bs[c][kb + tg + 4];
            }
#pragma unroll
            for (int i = 0; i < 4; i++)
#pragma unroll
                for (int jx = 0; jx < 4; jx++)
                    mma_tf32(acc[i][jx], a[i], b[jx]);
        }
        __syncthreads();
    }

#pragma unroll
    for (int i = 0; i < 4; i++) {
        int r0 = m0 + wm * 64 + i * 16 + g;
#pragma unroll
        for (int jx = 0; jx < 4; jx++) {
            int col = n0 + wn * 32 + jx * 8 + tg * 2;
            float2 bv = *(const float2*)(bias + col);
            float2 o0 = make_float2(acc[i][jx][0] + bv.x, acc[i][jx][1] + bv.y);
            float2 o1 = make_float2(acc[i][jx][2] + bv.x, acc[i][jx][3] + bv.y);
            *(float2*)(C + (size_t)r0 * G3H + col)       = o0;
            *(float2*)(C + (size_t)(r0 + 8) * G3H + col) = o1;
        }
    }
}

// ---------------------------------------------------------------------------
// MERGED two-layer GRU (round-10 topology, fp16 weights, fp16 SINGLE h).
// 257 windows. Window t:
//   warps 0-7  (task 0): h0(t)   = GRU0(h0(t-1), xg0[t])          [t < 256]
//   warps 8-15 (task 1): h1(t-1) = GRU1(h1(t-2), y0(t-1)=h0(t-1)) [t >= 1]
// hreg (the actual recurrent state) stays fp32 in registers; only the
// cross-block GEMM operand is fp16-quantized. Whh0+Whh1 frags in smem (96KB);
// Wih1 frags from L2 table. 2-ks ring prefetch on all task-1 streams.
// ---------------------------------------------------------------------------
__global__ void __launch_bounds__(512, 1) gru_merged_kernel(
    const float* __restrict__ Whh0, const float* __restrict__ bhh0,
    const float* __restrict__ Whh1, const float* __restrict__ bhh1,
    const float* __restrict__ bih1)
{
    extern __shared__ char smraw[];
    uint2* Wf = (uint2*)smraw;   // slots 0-5: Whh0, slots 6-11: Whh1 (96KB)

    const int tid = threadIdx.x;
    const int bid = blockIdx.x;
    const int jt = bid & 31, mt = bid >> 5;
    const int m0 = mt * 64, j0 = jt * 16;
    const int w = tid >> 5, lane = tid & 31;
    const int task = w >> 3, wsub = w & 7;
    const int wm = wsub >> 1, wn = wsub & 1;
    const int g = lane >> 2, tg = lane & 3;
    const int m16 = mt * 4 + wm;

    unsigned bgen = 0;
    if (tid < 32) bgen = g_slot[mt][jt][0];
    unsigned genc = 0;

    build_wfrag_f16((uint32_t*)Wf, Whh0, j0, tid, 0, 512);
    build_wfrag_f16((uint32_t*)Wf, Whh1, j0, tid, 6, 512);

    // Zero h0frag buf0 (h0(-1)) and h1frag buf1 (h1(-1)), group-local slices
    {
        int idx = (bid & 31) * 512 + tid;      // 0..16383
        size_t base = (size_t)mt * 4096;
        uint4 z = make_uint4(0, 0, 0, 0);
        if      (idx < 4096) g_h0frag[0][base + idx] = z;
        else if (idx < 8192) g_h1frag[1][base + idx - 4096] = z;
    }

    const int jc    = j0 + wn * 8 + 2 * tg;   // this thread's first j column
    const int mrow0 = m0 + wm * 16 + g;       // this thread's rows
    const int mrow1 = mrow0 + 8;

    // biases
    float br0[2], bz0[2], bn0[2];             // task 0
    float Br1[2], Bz1[2], bxn1[2], bhn1[2];   // task 1
    if (task == 0) {
        br0[0] = bhh0[jc];          br0[1] = bhh0[jc + 1];
        bz0[0] = bhh0[H_ + jc];     bz0[1] = bhh0[H_ + jc + 1];
        bn0[0] = bhh0[2 * H_ + jc]; bn0[1] = bhh0[2 * H_ + jc + 1];
    } else {
#pragma unroll
        for (int c = 0; c < 2; c++) {
            Br1[c]  = bih1[jc + c] + bhh1[jc + c];
            Bz1[c]  = bih1[H_ + jc + c] + bhh1[H_ + jc + c];
            bxn1[c] = bih1[2 * H_ + jc + c];
            bhn1[c] = bhh1[2 * H_ + jc + c];
        }
    }

    float hreg[4] = {0.f, 0.f, 0.f, 0.f};
    float xr[4], xz[4], xn[4];

    auto prefetch_xg = [&](int tt) {
        size_t b0 = ((size_t)mrow0 * T_ + tt) * G3H + jc;
        size_t b1 = ((size_t)mrow1 * T_ + tt) * G3H + jc;
        float2 v;
        v = *(const float2*)(g_xg + b0);           xr[0] = v.x; xr[1] = v.y;
        v = *(const float2*)(g_xg + b0 + H_);      xz[0] = v.x; xz[1] = v.y;
        v = *(const float2*)(g_xg + b0 + 2 * H_);  xn[0] = v.x; xn[1] = v.y;
        v = *(const float2*)(g_xg + b1);           xr[2] = v.x; xr[3] = v.y;
        v = *(const float2*)(g_xg + b1 + H_);      xz[2] = v.x; xz[3] = v.y;
        v = *(const float2*)(g_xg + b1 + 2 * H_);  xn[2] = v.x; xn[3] = v.y;
    };
    if (task == 0) prefetch_xg(0);

    slot_barrier(mt, jt, bgen + (++genc));

    const size_t fb0 = (size_t)(m16 * 32) * 32 + lane;
    const size_t sb  = ((size_t)(m16 * 32) + jt) * 32 + lane;
    const uint2* __restrict__ Wg = g_wfrag1 + (size_t)jt * 6144;  // Wih1 table

    for (int t = 0; t <= T_; t++) {
        if (task == 0) {
            if (t < T_) {
                float C[3][4];
                gemm48_h(C, Wf, wn * 3, g_h0frag[t & 1], fb0, lane);

                float hv[4];
#pragma unroll
                for (int i = 0; i < 4; i++) {
                    float r  = sigf(xr[i] + C[0][i] + br0[i & 1]);
                    float z  = sigf(xz[i] + C[1][i] + bz0[i & 1]);
                    float nv = tanhf(xn[i] + r * (C[2][i] + bn0[i & 1]));
                    float h  = (1.0f - z) * nv + z * hreg[i];
                    hreg[i] = h; hv[i] = h;
                }
                uint2 hiu = make_uint2(pack2_f16(hv[0], hv[1]), pack2_f16(hv[2], hv[3]));
                const int nb = (t + 1) & 1;
                ((uint2*)&g_h0frag[nb][sb])[wn] = hiu;

                if (t < T_ - 1) prefetch_xg(t + 1);
            }
        } else if (t >= 1) {
            const uint4* __restrict__ A0 = g_h0frag[t & 1];
            const uint4* __restrict__ A1 = g_h1frag[t & 1];

            // 6 independent accumulator chains: {r,z,n} x {ih, hh}
            float Cri[4] = {}, Crh[4] = {}, Czi[4] = {}, Czh[4] = {};
            float Cni[4] = {}, Cnh[4] = {};

            // 2-ks ring prefetch on A0, A1 and the L2 Wg streams
            uint4 a0b[2], a1b[2];
            uint2 wib[2][3];
            a0b[0] = A0[fb0];      a0b[1] = A0[fb0 + 32];
            a1b[0] = A1[fb0];      a1b[1] = A1[fb0 + 32];
#pragma unroll
            for (int s = 0; s < 3; s++) {
                wib[0][s] = Wg[((wn * 3 + s) * 32 + 0) * 32 + lane];
                wib[1][s] = Wg[((wn * 3 + s) * 32 + 1) * 32 + lane];
            }

#pragma unroll 4
            for (int ks = 0; ks < 32; ks++) {
                const int pb = ks & 1;
                uint4 a0 = a0b[pb], a1 = a1b[pb];
                uint2 wi0 = wib[pb][0], wi1 = wib[pb][1], wi2 = wib[pb][2];
                if (ks + 2 < 32) {
                    size_t nf = fb0 + (ks + 2) * 32;
                    a0b[pb] = A0[nf];
                    a1b[pb] = A1[nf];
                    wib[pb][0] = Wg[((wn * 3 + 0) * 32 + ks + 2) * 32 + lane];
                    wib[pb][1] = Wg[((wn * 3 + 1) * 32 + ks + 2) * 32 + lane];
                    wib[pb][2] = Wg[((wn * 3 + 2) * 32 + ks + 2) * 32 + lane];
                }
                // hh-side (Whh1, smem slots 6..11) against h1(t-2)
                uint2 wh0 = Wf[((6 + wn * 3 + 0) * 32 + ks) * 32 + lane];
                mma_f16(Crh, a1, wh0.x, wh0.y);
                uint2 wh1 = Wf[((6 + wn * 3 + 1) * 32 + ks) * 32 + lane];
                mma_f16(Czh, a1, wh1.x, wh1.y);
                uint2 wh2 = Wf[((6 + wn * 3 + 2) * 32 + ks) * 32 + lane];
                mma_f16(Cnh, a1, wh2.x, wh2.y);
                // ih-side (Wih1, global table) against h0(t-1)
                mma_f16(Cri, a0, wi0.x, wi0.y);
                mma_f16(Czi, a0, wi1.x, wi1.y);
                mma_f16(Cni, a0, wi2.x, wi2.y);
            }

            float hv[4];
#pragma unroll
            for (int i = 0; i < 4; i++) {
                float r  = sigf(Cri[i] + Crh[i] + Br1[i & 1]);
                float z  = sigf(Czi[i] + Czh[i] + Bz1[i & 1]);
                float nv = tanhf(Cni[i] + bxn1[i & 1] + r * (Cnh[i] + bhn1[i & 1]));
                float h  = (1.0f - z) * nv + z * hreg[i];
                hreg[i] = h; hv[i] = h;
            }
            if (t == T_) {
                *(float2*)(g_hT + (size_t)mrow0 * H_ + jc) = make_float2(hv[0], hv[1]);
                *(float2*)(g_hT + (size_t)mrow1 * H_ + jc) = make_float2(hv[2], hv[3]);
            } else {
                uint2 hiu = make_uint2(pack2_f16(hv[0], hv[1]), pack2_f16(hv[2], hv[3]));
                const int nb = (t + 1) & 1;
                ((uint2*)&g_h1frag[nb][sb])[wn] = hiu;
            }
        }

        slot_barrier(mt, jt, bgen + (++genc));
    }
}

// ---------------------------------------------------------------------------
// Head: out = relu(relu(hT) @ fc1^T + b1) @ fc2^T + b2
// ---------------------------------------------------------------------------
__global__ void __launch_bounds__(512) head_kernel(
    const float* __restrict__ w1, const float* __restrict__ b1,
    const float* __restrict__ w2, const float* __restrict__ b2,
    float* __restrict__ out)
{
    __shared__ float sh[H_];
    __shared__ float s1[128];
    const int b = blockIdx.x;
    const int tid = threadIdx.x;
    const int w = tid >> 5, lane = tid & 31;

    sh[tid] = fmaxf(g_hT[(size_t)b * H_ + tid], 0.0f);
    __syncthreads();

#pragma unroll
    for (int oo = 0; oo < 8; oo++) {
        int o = w * 8 + oo;
        const float* wr = w1 + (size_t)o * H_;
        float acc = 0.f;
#pragma unroll
        for (int c = 0; c < 4; c++) {
            int k = c * 128 + lane * 4;
            float4 wv = *(const float4*)(wr + k);
            float4 hv = *(const float4*)(&sh[k]);
            acc += wv.x * hv.x + wv.y * hv.y + wv.z * hv.z + wv.w * hv.w;
        }
#pragma unroll
        for (int off = 16; off; off >>= 1)
            acc += __shfl_down_sync(0xFFFFFFFFu, acc, off);
        if (lane == 0) s1[o] = fmaxf(acc + b1[o], 0.0f);
    }
    __syncthreads();

    if (w < 10) {
        const float* wr = w2 + (size_t)w * 128;
        float acc = 0.f;
#pragma unroll
        for (int c = 0; c < 4; c++) {
            int k = lane + c * 32;
            acc += s1[k] * wr[k];
        }
#pragma unroll
        for (int off = 16; off; off >>= 1)
            acc += __shfl_down_sync(0xFFFFFFFFu, acc, off);
        if (lane == 0) out[(size_t)b * 10 + w] = acc + b2[w];
    }
}

// ---------------------------------------------------------------------------
// Launch
// ---------------------------------------------------------------------------
extern "C" void kernel_launch(void* const* d_in, const int* in_sizes, int n_in,
                              void* d_out, int out_size)
{
    const float* x    = (const float*)d_in[0];
    const float* Wih0 = (const float*)d_in[1];
    const float* Whh0 = (const float*)d_in[2];
    const float* bih0 = (const float*)d_in[3];
    const float* bhh0 = (const float*)d_in[4];
    const float* Wih1 = (const float*)d_in[5];
    const float* Whh1 = (const float*)d_in[6];
    const float* bih1 = (const float*)d_in[7];
    const float* bhh1 = (const float*)d_in[8];
    const float* fc1w = (const float*)d_in[9];
    const float* fc1b = (const float*)d_in[10];
    const float* fc2w = (const float*)d_in[11];
    const float* fc2b = (const float*)d_in[12];
    float* out = (float*)d_out;

    float* xg_ptr = nullptr;
    cudaGetSymbolAddress((void**)&xg_ptr, g_xg);

    const int merged_smem = 12 * 32 * 32 * 8;   // 96KB
    cudaFuncSetAttribute((const void*)gru_merged_kernel,
                         cudaFuncAttributeMaxDynamicSharedMemorySize, merged_smem);

    dim3 gemm_grid(G3H / 128, BT / 128);  // (12, 512)

    // Phase 0: Wih1 fp16 fragment table (1.5MB, L2-resident)
    build_wih1_kernel<<<32, 512>>>(Wih1);

    // Phase 1: xg0 = x @ W_ih0^T + b_ih0   (K = 128)
    gemm_tf32_kernel<<<gemm_grid, 256>>>(x, Wih0, bih0, D_, xg_ptr);

    // Phase 2: merged two-layer GRU (257 barrier windows)
    gru_merged_kernel<<<128, 512, merged_smem>>>(Whh0, bhh0, Whh1, bhh1, bih1);

    // Phase 3: MLP head
    head_kernel<<<B_, 512>>>(fc1w, fc1b, fc2w, fc2b, out);
}